// round 5
// baseline (speedup 1.0000x reference)
#include <cuda_runtime.h>
#include <cuda_bf16.h>
#include <math.h>
#include <stdint.h>

// VectorQuantizerEMA: D=64, K=512, N=B*T=262144.
// Legacy HMMA (mma.sync bf16, fp32 accum) hi/lo-split screen + exact fp32 rescore
// whose arithmetic is bit-identical to the known-passing scalar kernel.
#define DIM 64
#define NCODES 512
#define TILE_M 128
#define TPB 256
#define GRID 152
#define NCHUNK 32          // 512 codes / 16
#define CMIN_STRIDE 33     // padded to avoid bank conflicts

__device__ float g_part[GRID];

// ---------- smem layout (bytes) ----------
#define OFF_AH    0                       // A hi  [128 x 128B] bf16 SW128
#define OFF_AL    (OFF_AH + 16384)        // A lo
#define OFF_BH    (OFF_AL + 16384)        // B hi  [512 x 128B]
#define OFF_BL    (OFF_BH + 65536)        // B lo
#define OFF_EEW   (OFF_BL + 65536)        // float4[512]: (ee, w, s, 0)
#define OFF_CMIN  (OFF_EEW + 8192)        // float[128][33] chunk mins
#define OFF_TROW  (OFF_CMIN + 128*CMIN_STRIDE*4)  // float[128] row min
#define OFF_SXX   (OFF_TROW + 512)        // float[128] row ||x||^2
#define OFF_SMAX  (OFF_SXX + 512)         // float: max_k s_k
#define OFF_RED   (OFF_SMAX + 16)         // loss reduction [256]
#define SMEM_TOTAL (OFF_RED + TPB*4)

#define SWZ(o) ((uint32_t)(o) ^ ((((uint32_t)(o)) >> 3) & 0x70))

__device__ __forceinline__ uint32_t smem_u32(const void* p) {
    uint32_t a;
    asm("{ .reg .u64 t; cvta.to.shared.u64 t, %1; cvt.u32.u64 %0, t; }"
        : "=r"(a) : "l"(p));
    return a;
}
__device__ __forceinline__ void ldm4(uint32_t* r, uint32_t addr) {
    asm volatile("ldmatrix.sync.aligned.m8n8.x4.shared.b16 {%0,%1,%2,%3}, [%4];"
                 : "=r"(r[0]), "=r"(r[1]), "=r"(r[2]), "=r"(r[3]) : "r"(addr));
}
__device__ __forceinline__ void mma16816(float* c, const uint32_t* a,
                                         const uint32_t* b) {
    asm volatile(
        "mma.sync.aligned.m16n8k16.row.col.f32.bf16.bf16.f32 "
        "{%0,%1,%2,%3}, {%4,%5,%6,%7}, {%8,%9}, {%0,%1,%2,%3};"
        : "+f"(c[0]), "+f"(c[1]), "+f"(c[2]), "+f"(c[3])
        : "r"(a[0]), "r"(a[1]), "r"(a[2]), "r"(a[3]), "r"(b[0]), "r"(b[1]));
}
// split float pair -> packed bf16 hi / bf16 lo(residual)
__device__ __forceinline__ void split2(float a, float b, uint32_t& hi, uint32_t& lo) {
    __nv_bfloat16 ha = __float2bfloat16(a), hb = __float2bfloat16(b);
    float ra = a - __bfloat162float(ha);
    float rb = b - __bfloat162float(hb);
    __nv_bfloat16 la = __float2bfloat16(ra), lb = __float2bfloat16(rb);
    hi = ((uint32_t)__bfloat16_as_ushort(hb) << 16) | (uint32_t)__bfloat16_as_ushort(ha);
    lo = ((uint32_t)__bfloat16_as_ushort(lb) << 16) | (uint32_t)__bfloat16_as_ushort(la);
}

__global__ void __launch_bounds__(TPB, 1)
vq_hmma(const float* __restrict__ inputs,
        const float* __restrict__ emb,
        const float* __restrict__ ema,
        float* __restrict__ out_q,
        float* __restrict__ out_idx,
        int ntiles) {
    extern __shared__ char smem[];
    const uint32_t sbase = smem_u32(smem);
    const int tid  = threadIdx.x;
    const int wid  = tid >> 5;
    const int lane = tid & 31;

    float4* eew  = (float4*)(smem + OFF_EEW);
    float*  cmin = (float*)(smem + OFF_CMIN);
    float*  trow = (float*)(smem + OFF_TROW);
    float*  sxx  = (float*)(smem + OFF_SXX);

    if (tid == 0) *(int*)(smem + OFF_SMAX) = 0;
    __syncthreads();

    // ---- codebook init: bf16 hi/lo planes + (ee, w, s) ----
    // ee computed with SERIAL scalar fma chain: bit-identical to the passing
    // round-2 scalar kernel (grouped sums differ by ulps and flip near-ties).
    for (int k = tid; k < NCODES; k += TPB) {
        const float* e = emb + k * DIM;
        float ee = 0.f;
#pragma unroll
        for (int d = 0; d < DIM; d++) ee += e[d] * e[d];

        const float4* ep = (const float4*)e;
#pragma unroll
        for (int q = 0; q < 16; q++) {
            float4 e4 = ep[q];
            uint32_t h0, l0, h1, l1;
            split2(e4.x, e4.y, h0, l0);
            split2(e4.z, e4.w, h1, l1);
            uint32_t o0 = SWZ(k * 128 + q * 8);
            uint32_t o1 = SWZ(k * 128 + q * 8 + 4);
            *(uint32_t*)(smem + OFF_BH + o0) = h0;
            *(uint32_t*)(smem + OFF_BH + o1) = h1;
            *(uint32_t*)(smem + OFF_BL + o0) = l0;
            *(uint32_t*)(smem + OFF_BL + o1) = l1;
        }
        float w = sqrtf(ema[k]);
        float s = sqrtf(ee) * w;
        eew[k] = make_float4(ee, w, s, 0.f);
        atomicMax((int*)(smem + OFF_SMAX), __float_as_int(s));  // s >= 0
    }
    __syncthreads();
    const float smax = *(float*)(smem + OFF_SMAX);

    // per-lane fragment geometry (fixed)
    const int R0 = wid * 16;
    const int rowA = R0 + ((lane >> 3) & 1) * 8 + (lane & 7);
    const uint32_t kaddA = ((lane >> 4) & 1) * 16;
    const int rowB = ((lane >> 4) & 1) * 8 + (lane & 7);
    const uint32_t kaddB = ((lane >> 3) & 1) * 16;
    const int rrow0 = R0 + (lane >> 2);     // epilogue rows
    const int rrow1 = rrow0 + 8;
    const int jcol  = (lane & 3) * 2;       // epilogue col base within chunk

    float lsum = 0.f;

    for (int tile = blockIdx.x; tile < ntiles; tile += GRID) {
        const size_t base = (size_t)tile * TILE_M;
        __syncthreads();  // prev-tile phase2 done; safe to overwrite A/cmin

        // ---- A tile: registers + bf16 hi/lo planes + xx (round-2 shape) ----
        float4 xr[16];
        float xxr = 0.f;
        if (tid < TILE_M) {
            const float4* xp = (const float4*)(inputs + (base + tid) * DIM);
#pragma unroll
            for (int q = 0; q < 16; q++) xr[q] = xp[q];
#pragma unroll
            for (int q = 0; q < 16; q++) {
                float4 v = xr[q];
                xxr += v.x * v.x + v.y * v.y + v.z * v.z + v.w * v.w;
            }
#pragma unroll
            for (int q = 0; q < 16; q++) {
                float4 v = xr[q];
                uint32_t h0, l0, h1, l1;
                split2(v.x, v.y, h0, l0);
                split2(v.z, v.w, h1, l1);
                uint32_t o0 = SWZ(tid * 128 + q * 8);
                uint32_t o1 = SWZ(tid * 128 + q * 8 + 4);
                *(uint32_t*)(smem + OFF_AH + o0) = h0;
                *(uint32_t*)(smem + OFF_AH + o1) = h1;
                *(uint32_t*)(smem + OFF_AL + o0) = l0;
                *(uint32_t*)(smem + OFF_AL + o1) = l1;
            }
            sxx[tid] = xxr;
        }
        __syncthreads();  // A ready

        // ---- GEMM screen phase (all 8 warps) ----
        uint32_t ahi[4][4], alo[4][4];
#pragma unroll
        for (int s = 0; s < 4; s++) {
            uint32_t off = SWZ(rowA * 128 + s * 32 + kaddA);
            ldm4(ahi[s], sbase + OFF_AH + off);
            ldm4(alo[s], sbase + OFF_AL + off);
        }

        const float xx0 = sxx[rrow0];
        const float xx1 = sxx[rrow1];
        float dmin0 = __int_as_float(0x7f800000);
        float dmin1 = __int_as_float(0x7f800000);

#pragma unroll 1
        for (int c = 0; c < NCHUNK; c++) {
            const int n0 = c * 16;
            float acc0[4] = {0.f, 0.f, 0.f, 0.f};
            float acc1[4] = {0.f, 0.f, 0.f, 0.f};
#pragma unroll
            for (int s = 0; s < 4; s++) {
                uint32_t boff = SWZ((n0 + rowB) * 128 + s * 32 + kaddB);
                uint32_t bh[4], bl[4];
                ldm4(bh, sbase + OFF_BH + boff);
                mma16816(acc0, ahi[s], bh + 0);
                mma16816(acc1, ahi[s], bh + 2);
                mma16816(acc0, alo[s], bh + 0);
                mma16816(acc1, alo[s], bh + 2);
                ldm4(bl, sbase + OFF_BL + boff);
                mma16816(acc0, ahi[s], bl + 0);
                mma16816(acc1, ahi[s], bl + 2);
            }
            // epilogue: screened distances for this 16x16 chunk
            float4 e00 = eew[n0 + jcol];
            float4 e01 = eew[n0 + jcol + 1];
            float4 e10 = eew[n0 + jcol + 8];
            float4 e11 = eew[n0 + jcol + 9];
            float w2a = -2.f * e00.y, w2b = -2.f * e01.y;
            float w2c = -2.f * e10.y, w2d = -2.f * e11.y;
            float d00 = fmaf(acc0[0], w2a, (xx0 + e00.x) * e00.y);
            float d01 = fmaf(acc0[1], w2b, (xx0 + e01.x) * e01.y);
            float d02 = fmaf(acc1[0], w2c, (xx0 + e10.x) * e10.y);
            float d03 = fmaf(acc1[1], w2d, (xx0 + e11.x) * e11.y);
            float d10 = fmaf(acc0[2], w2a, (xx1 + e00.x) * e00.y);
            float d11 = fmaf(acc0[3], w2b, (xx1 + e01.x) * e01.y);
            float d12 = fmaf(acc1[2], w2c, (xx1 + e10.x) * e10.y);
            float d13 = fmaf(acc1[3], w2d, (xx1 + e11.x) * e11.y);
            float m0 = fminf(fminf(d00, d01), fminf(d02, d03));
            float m1 = fminf(fminf(d10, d11), fminf(d12, d13));
            m0 = fminf(m0, __shfl_xor_sync(0xffffffffu, m0, 1));
            m0 = fminf(m0, __shfl_xor_sync(0xffffffffu, m0, 2));
            m1 = fminf(m1, __shfl_xor_sync(0xffffffffu, m1, 1));
            m1 = fminf(m1, __shfl_xor_sync(0xffffffffu, m1, 2));
            dmin0 = fminf(dmin0, m0);
            dmin1 = fminf(dmin1, m1);
            if ((lane & 3) == 0) {
                cmin[rrow0 * CMIN_STRIDE + c] = m0;
                cmin[rrow1 * CMIN_STRIDE + c] = m1;
            }
        }
        if ((lane & 3) == 0) {
            trow[rrow0] = dmin0;
            trow[rrow1] = dmin1;
        }
        __syncthreads();  // cmin/trow ready

        // ---- phase 2: exact fp32 rescore of flagged chunks ----
        if (tid < TILE_M) {
            // analytic screen error <= 2.3e-5*||x||*s_k; margin 26x + abs slack
            float errmax = fmaf(6e-4f, sqrtf(xxr) * smax, 4e-3f);
            float thr = trow[tid] + 2.f * errmax;

            float best = __int_as_float(0x7f800000);
            int bk = 0;
#pragma unroll 1
            for (int c = 0; c < NCHUNK; c++) {
                if (cmin[tid * CMIN_STRIDE + c] > thr) continue;
#pragma unroll 1
                for (int kk = 0; kk < 16; kk++) {
                    int k = c * 16 + kk;
                    const float4* ep = (const float4*)(emb + k * DIM);
                    float s0 = 0.f, s1 = 0.f, s2 = 0.f, s3 = 0.f;
#pragma unroll
                    for (int q = 0; q < 16; q++) {
                        float4 e4 = __ldg(ep + q);
                        s0 = fmaf(xr[q].x, e4.x, s0);
                        s1 = fmaf(xr[q].y, e4.y, s1);
                        s2 = fmaf(xr[q].z, e4.z, s2);
                        s3 = fmaf(xr[q].w, e4.w, s3);
                    }
                    float d = (s0 + s1) + (s2 + s3);
                    float4 ew = eew[k];
                    float t = (xxr + ew.x - 2.0f * d) * ew.y;
                    if (t < best) { best = t; bk = k; }
                }
            }
            // outputs
            const float4* ep = (const float4*)(emb + bk * DIM);
            float4* oq = (float4*)(out_q + (base + tid) * DIM);
#pragma unroll
            for (int q = 0; q < 16; q++) {
                float4 e4 = __ldg(ep + q);
                float dx = xr[q].x - e4.x, dy = xr[q].y - e4.y;
                float dz = xr[q].z - e4.z, dw = xr[q].w - e4.w;
                lsum += dx * dx + dy * dy + dz * dz + dw * dw;
                oq[q] = e4;
            }
            out_idx[base + tid] = (float)bk;
        }
    }

    // ---- loss block reduction ----
    __syncthreads();
    float* red = (float*)(smem + OFF_RED);
    red[tid] = lsum;
    __syncthreads();
#pragma unroll
    for (int s = TPB / 2; s > 0; s >>= 1) {
        if (tid < s) red[tid] += red[tid + s];
        __syncthreads();
    }
    if (tid == 0) g_part[blockIdx.x] = red[0];
}

__global__ void vq_finalize(float* __restrict__ out_loss, float inv_count) {
    __shared__ float buf[256];
    float s = 0.f;
    for (int i = threadIdx.x; i < GRID; i += 256) s += g_part[i];
    buf[threadIdx.x] = s;
    __syncthreads();
#pragma unroll
    for (int st = 128; st > 0; st >>= 1) {
        if (threadIdx.x < st) buf[threadIdx.x] += buf[threadIdx.x + st];
        __syncthreads();
    }
    if (threadIdx.x == 0) out_loss[0] = 0.25f * buf[0] * inv_count;
}

extern "C" void kernel_launch(void* const* d_in, const int* in_sizes, int n_in,
                              void* d_out, int out_size) {
    const float* inputs = (const float*)d_in[0];
    const float* emb    = (const float*)d_in[1];
    const float* ema    = (const float*)d_in[2];

    int N = in_sizes[0] / DIM;
    int ntiles = N / TILE_M;
    float* out = (float*)d_out;
    float* out_q    = out;
    float* out_loss = out + (size_t)N * DIM;
    float* out_idx  = out + (size_t)N * DIM + 1;

    static bool attr_done = false;
    if (!attr_done) {
        cudaFuncSetAttribute(vq_hmma, cudaFuncAttributeMaxDynamicSharedMemorySize,
                             SMEM_TOTAL);
        attr_done = true;
    }

    vq_hmma<<<GRID, TPB, SMEM_TOTAL>>>(inputs, emb, ema, out_q, out_idx, ntiles);
    vq_finalize<<<1, 256>>>(out_loss, 1.0f / ((float)N * (float)DIM));
}